// round 16
// baseline (speedup 1.0000x reference)
#include <cuda_runtime.h>
#include <cuda_bf16.h>
#include <cstdint>

// ---------------------------------------------------------------------------
// fused: out = relu(x@Wc^T + mean_k(x[nh])@Wn^T + mean_k(e)@We^T)
// mma.sync m16n8k8 tf32; M=64 rows/tile, N=128, K=320 = [x|mean x[nh]|mean e]
// 2 CTAs/SM (101KB SMEM each), 512 thr/CTA. ij int32. Streaming e/ij/out.
// R16 = R15 (bf16 gather table; main kernel 181us) + PDL overlap:
//   main kernel launches with programmatic stream serialization; its A-build
//   runs ij/self-x/e-mean BEFORE cudaGridDependencySynchronize(), so wave-1
//   CTAs overlap the ~12us x->bf16 pre-pass instead of serializing behind it.
// ---------------------------------------------------------------------------

#define FULLMASK 0xFFFFFFFFu

static constexpr int NR     = 100000;
static constexpr int TM     = 64;                   // rows per tile
static constexpr int NTILES = (NR + TM - 1) / TM;   // 1563
static constexpr int AS     = 324;                  // A smem stride (floats)
static constexpr int WS     = 20;                   // W chunk stride (floats)
static constexpr int KCH    = 16;                   // K per W chunk
static constexpr int NCH    = 20;                   // 20 * 16 = 320
static constexpr int NTHR   = 512;
static constexpr unsigned A_BYTES = TM * AS * 4;        // 82944
static constexpr unsigned WBUF_B  = 128 * WS * 4;       // 10240 per buffer
static constexpr unsigned SMEM_DYN = A_BYTES + 2 * WBUF_B;  // 103424 -> 2 CTAs/SM

// bf16 copy of x for the neighbor gather (25.6 MB device scratch)
__device__ __nv_bfloat16 xbf_g[(size_t)NR * 128];

static __device__ __forceinline__ uint32_t smem_u32(const void* p) {
    uint32_t a;
    asm("{ .reg .u64 t; cvta.to.shared.u64 t, %1; cvt.u32.u64 %0, t; }"
        : "=r"(a) : "l"(p));
    return a;
}

static __device__ __forceinline__ uint32_t f2tf(float f) {
    uint32_t r;
    asm("cvt.rna.tf32.f32 %0, %1;" : "=r"(r) : "f"(f));
    return r;
}

static __device__ __forceinline__ void mma8(float* c, const uint32_t* a,
                                            uint32_t b0, uint32_t b1) {
    asm volatile(
        "mma.sync.aligned.m16n8k8.row.col.f32.tf32.tf32.f32 "
        "{%0,%1,%2,%3}, {%4,%5,%6,%7}, {%8,%9}, {%0,%1,%2,%3};"
        : "+f"(c[0]), "+f"(c[1]), "+f"(c[2]), "+f"(c[3])
        : "r"(a[0]), "r"(a[1]), "r"(a[2]), "r"(a[3]), "r"(b0), "r"(b1));
}

#define LDSM_X4(r0, r1, r2, r3, addr)                                          \
    asm volatile("ldmatrix.sync.aligned.m8n8.x4.shared.b16 {%0,%1,%2,%3}, [%4];" \
                 : "=r"(r0), "=r"(r1), "=r"(r2), "=r"(r3) : "r"(addr))

// ---------------- pre-pass: x (fp32) -> xbf_g (bf16) -----------------------
__global__ void __launch_bounds__(256)
cvt_x_bf16(const float* __restrict__ x)
{
    const int i = blockIdx.x * 256 + threadIdx.x;   // float4 index
    if (i < NR * 32) {
        const float4 v = __ldcs((const float4*)x + i);
        const __nv_bfloat162 a = __floats2bfloat162_rn(v.x, v.y);
        const __nv_bfloat162 b = __floats2bfloat162_rn(v.z, v.w);
        uint2 p;
        p.x = *(const uint32_t*)&a;
        p.y = *(const uint32_t*)&b;
        *(uint2*)(xbf_g + (size_t)i * 4) = p;
    }
}

__global__ void __launch_bounds__(NTHR, 2)
conv_block_fused(const float* __restrict__ x, const float* __restrict__ e,
                 const int* __restrict__ ij,
                 const float* __restrict__ Wc, const float* __restrict__ Wn,
                 const float* __restrict__ We, float* __restrict__ out)
{
    extern __shared__ uint32_t smem[];
    uint32_t* As = smem;                        // A tile, tf32 bits, [64][AS]
    uint32_t* Wb = smem + TM * AS;              // W buffers, 2 x [128][WS]

    const int tid  = threadIdx.x;
    const int wid  = tid >> 5;       // 0..15
    const int lane = tid & 31;
    const int gid  = lane >> 2;      // 0..7
    const int tq   = lane & 3;       // 0..3
    const int row0 = blockIdx.x * TM;

    const float inv = 1.0f / 16.0f;
    const int r0  = wid * 4;
    const int rgb = row0 + r0;

    // ---- A-build phase 1 (no dependence on the bf16 table) ---------------
    // ij prefetch for this warp's 4 rows (2 streamed LDGs)
    int nh01 = 0, nh23 = 0;
    {
        const int rowsel = lane >> 4;       // 0 or 1
        const int nidx   = lane & 15;
        const int ra = rgb + rowsel;
        const int rb = rgb + 2 + rowsel;
        if (ra < NR) nh01 = __ldcs(ij + ra * 32 + nidx * 2);
        if (rb < NR) nh23 = __ldcs(ij + rb * 32 + nidx * 2);
    }

    #pragma unroll 1
    for (int rr = 0; rr < 4; rr++) {
        const int r  = r0 + rr;
        const int rg = row0 + r;
        const bool valid = (rg < NR);

        float4 xv = make_float4(0.f, 0.f, 0.f, 0.f);
        float2 ea = make_float2(0.f, 0.f);
        if (valid) {
            // self row: read-once (gather uses the bf16 table)
            xv = __ldcs((const float4*)(x + rg * 128) + lane);
            // e is a read-once stream: evict-first
            const float2* ep = (const float2*)(e + rg * 1024 + lane * 2);
            #pragma unroll
            for (int k = 0; k < 16; k++) {
                const float2 t = __ldcs(ep + k * 32);
                ea.x += t.x; ea.y += t.y;
            }
        }
        ea.x *= inv; ea.y *= inv;

        uint32_t* a0 = As + r * AS + lane * 4;
        a0[0] = f2tf(xv.x); a0[1] = f2tf(xv.y); a0[2] = f2tf(xv.z); a0[3] = f2tf(xv.w);
        uint32_t* a2 = As + r * AS + 256 + lane * 2;
        a2[0] = f2tf(ea.x); a2[1] = f2tf(ea.y);
    }

    // ---- wait for the pre-pass grid (PDL) before touching the table ------
    cudaGridDependencySynchronize();

    // ---- A-build phase 2: neighbor gathers from the bf16 table -----------
    #pragma unroll 1
    for (int rr = 0; rr < 4; rr++) {
        const int r  = r0 + rr;
        const int rg = row0 + r;
        const bool valid = (rg < NR);

        const int nsrc = (rr < 2) ? nh01 : nh23;
        int rk[16];
        #pragma unroll
        for (int k = 0; k < 16; k++)
            rk[k] = __shfl_sync(FULLMASK, nsrc, (rr & 1) * 16 + k);

        float4 ac = make_float4(0.f, 0.f, 0.f, 0.f);
        if (valid) {
            #pragma unroll
            for (int k = 0; k < 16; k++) {
                const uint2 t = *(const uint2*)(xbf_g + (size_t)rk[k] * 128 + lane * 4);
                const float2 lo = __bfloat1622float2(*(const __nv_bfloat162*)&t.x);
                const float2 hi = __bfloat1622float2(*(const __nv_bfloat162*)&t.y);
                ac.x += lo.x; ac.y += lo.y; ac.z += hi.x; ac.w += hi.y;
            }
        }
        ac.x *= inv; ac.y *= inv; ac.z *= inv; ac.w *= inv;

        uint32_t* a1 = As + r * AS + 128 + lane * 4;
        a1[0] = f2tf(ac.x); a1[1] = f2tf(ac.y); a1[2] = f2tf(ac.z); a1[3] = f2tf(ac.w);
    }

    // ---------------- GEMM: mma.sync tf32, warp tile 16(M) x 32(N) --------
    const int m0 = (wid & 3) * 16;
    const int n0 = (wid >> 2) * 32;

    const uint32_t sb  = smem_u32(smem);
    const uint32_t Wsb = sb + A_BYTES;
    const int t8 = lane >> 3;        // tile index 0..3
    const int w8 = lane & 7;         // row within tile
    const uint32_t a_lane = sb +
        (((m0 + (t8 & 1) * 8 + w8) * AS) + (t8 >> 1) * 4) * 4;
    const uint32_t b_lane1 = Wsb +
        (((n0 + (t8 >> 1) * 8 + w8) * WS) + (t8 & 1) * 4) * 4;
    const uint32_t b_lane2 = b_lane1 + 16 * WS * 4;   // j+2

    float acc[4][4];
    #pragma unroll
    for (int j = 0; j < 4; j++)
        #pragma unroll
        for (int q = 0; q < 4; q++) acc[j][q] = 0.f;

    // W gmem lane mapping: one float4 per thread per chunk
    const int nrow = tid >> 2;       // 0..127
    const int k4   = tid & 3;        // 0..3
    uint32_t* wdst_base = Wb + nrow * WS + k4 * 4;

    // preload chunk 0 (Wc, koff 0)
    {
        const float4 v = *(const float4*)(Wc + nrow * 128 + k4 * 4);
        uint32_t* d = wdst_base;     // buffer 0
        d[0] = f2tf(v.x); d[1] = f2tf(v.y); d[2] = f2tf(v.z); d[3] = f2tf(v.w);
    }
    __syncthreads();   // A tile + W chunk 0 ready

    #pragma unroll 1
    for (int c = 0; c < NCH; c++) {
        // issue next W chunk load early (latency hidden by compute)
        float4 wv;
        const int nc = c + 1;
        if (nc < NCH) {
            const float* src; int koff; int sk;
            if (nc < 8)       { src = Wc; koff = nc * 16;        sk = 128; }
            else if (nc < 16) { src = Wn; koff = (nc - 8) * 16;  sk = 128; }
            else              { src = We; koff = (nc - 16) * 16; sk = 64;  }
            wv = *(const float4*)(src + nrow * sk + koff + k4 * 4);
        }

        // compute 2 ksteps of this chunk
        const uint32_t abase = a_lane + (uint32_t)(c * KCH * 4);
        const uint32_t wbase = (uint32_t)((c & 1) * (int)WBUF_B);
        #pragma unroll
        for (int s = 0; s < 2; s++) {
            uint32_t a[4], b0, b1, b2, b3, b4, b5, b6, b7;
            LDSM_X4(a[0], a[1], a[2], a[3], abase + s * 32);
            LDSM_X4(b0, b1, b2, b3, b_lane1 + wbase + s * 32);
            LDSM_X4(b4, b5, b6, b7, b_lane2 + wbase + s * 32);
            mma8(acc[0], a, b0, b1);
            mma8(acc[1], a, b2, b3);
            mma8(acc[2], a, b4, b5);
            mma8(acc[3], a, b6, b7);
        }

        // store next chunk into the other buffer (its readers finished at bar c-1)
        if (nc < NCH) {
            uint32_t* d = wdst_base + (nc & 1) * (WBUF_B / 4);
            d[0] = f2tf(wv.x); d[1] = f2tf(wv.y); d[2] = f2tf(wv.z); d[3] = f2tf(wv.w);
        }
        __syncthreads();
    }

    // ---------------- epilogue: relu + store (write-once: streaming) ------
    {
        const int rg0 = row0 + m0 + gid;
        const int rg1 = rg0 + 8;
        #pragma unroll
        for (int j = 0; j < 4; j++) {
            const int col = n0 + j * 8 + tq * 2;
            if (rg0 < NR) {
                float2 v;
                v.x = fmaxf(acc[j][0], 0.f);
                v.y = fmaxf(acc[j][1], 0.f);
                __stcs((float2*)(out + rg0 * 128 + col), v);
            }
            if (rg1 < NR) {
                float2 v;
                v.x = fmaxf(acc[j][2], 0.f);
                v.y = fmaxf(acc[j][3], 0.f);
                __stcs((float2*)(out + rg1 * 128 + col), v);
            }
        }
    }
}

extern "C" void kernel_launch(void* const* d_in, const int* in_sizes, int n_in,
                              void* d_out, int out_size)
{
    (void)in_sizes; (void)n_in; (void)out_size;
    const float* x  = (const float*)d_in[0];
    const float* e  = (const float*)d_in[1];
    const int*   ij = (const int*)d_in[2];
    const float* Wc = (const float*)d_in[3];
    const float* Wn = (const float*)d_in[4];
    const float* We = (const float*)d_in[5];
    float* outp = (float*)d_out;

    // pre-pass: build bf16 gather table
    cvt_x_bf16<<<(NR * 32 + 255) / 256, 256>>>(x);

    // main kernel with programmatic dependent launch: wave-1 CTAs start
    // during the pre-pass and only block at cudaGridDependencySynchronize()
    cudaFuncSetAttribute(conv_block_fused,
                         cudaFuncAttributeMaxDynamicSharedMemorySize, SMEM_DYN);

    cudaLaunchConfig_t cfg = {};
    cfg.gridDim = dim3(NTILES, 1, 1);
    cfg.blockDim = dim3(NTHR, 1, 1);
    cfg.dynamicSmemBytes = SMEM_DYN;
    cfg.stream = 0;
    cudaLaunchAttribute attr[1];
    attr[0].id = cudaLaunchAttributeProgrammaticStreamSerialization;
    attr[0].val.programmaticStreamSerializationAllowed = 1;
    cfg.attrs = attr;
    cfg.numAttrs = 1;
    cudaLaunchKernelEx(&cfg, conv_block_fused, x, e, ij, Wc, Wn, We, outp);
}